// round 1
// baseline (speedup 1.0000x reference)
#include <cuda_runtime.h>

#define Bn 256
#define Cn 4096
#define Dn 100
#define MARGIN 0.1f

// Scratch accumulators (no allocations allowed -> __device__ globals)
__device__ double g_acc1;
__device__ double g_acc2;

__global__ void init_kernel() {
    g_acc1 = 0.0;
    g_acc2 = 0.0;
}

// loss1: mean((pos - lan)^2) over B*D = 25600 elements. One block.
__global__ void loss1_kernel(const float* __restrict__ pos,
                             const float* __restrict__ lan) {
    float acc = 0.f;
    for (int i = threadIdx.x; i < Bn * Dn; i += blockDim.x) {
        float d = pos[i] - lan[i];
        acc = fmaf(d, d, acc);
    }
    // intra-warp reduce
    #pragma unroll
    for (int o = 16; o; o >>= 1) acc += __shfl_xor_sync(0xffffffffu, acc, o);
    __shared__ float ws[8];
    if ((threadIdx.x & 31) == 0) ws[threadIdx.x >> 5] = acc;
    __syncthreads();
    if (threadIdx.x < 8) {
        float v = ws[threadIdx.x];
        #pragma unroll
        for (int o = 4; o; o >>= 1) v += __shfl_xor_sync(0xffu, v, o, 8);
        if (threadIdx.x == 0) atomicAdd(&g_acc1, (double)v);
    }
}

// loss2: each block handles one b and 64 consecutive c rows.
// 8 warps/block; warp w processes c = cbase + j*8 + w for j in 0..7.
// Each warp: reduce 100 floats per row (lanes stride 32, 4 iters).
// pos row loaded once into registers, reused for all 8 rows.
__global__ __launch_bounds__(256) void loss2_kernel(
    const float* __restrict__ pos, const float* __restrict__ neg) {
    const int warp = threadIdx.x >> 5;
    const int lane = threadIdx.x & 31;
    const int b = blockIdx.x >> 6;        // 64 blocks per b
    const int cbase = (blockIdx.x & 63) << 6;  // *64

    // Load pos[b, :] fragment for this lane (4 strided elements, last masked)
    const float* prow = pos + b * Dn;
    float p0 = prow[lane];
    float p1 = prow[lane + 32];
    float p2 = prow[lane + 64];
    float p3 = (lane + 96 < Dn) ? prow[lane + 96] : 0.f;

    __shared__ float bs;
    if (threadIdx.x == 0) bs = 0.f;
    __syncthreads();

    float hinge_sum = 0.f;

    #pragma unroll
    for (int j = 0; j < 8; j++) {
        const int c = cbase + j * 8 + warp;
        const float* nrow = neg + ((long long)b * Cn + c) * Dn;
        float d0 = p0 - nrow[lane];
        float d1 = p1 - nrow[lane + 32];
        float d2 = p2 - nrow[lane + 64];
        float d3 = (lane + 96 < Dn) ? (p3 - nrow[lane + 96]) : 0.f;
        float acc = d0 * d0;
        acc = fmaf(d1, d1, acc);
        acc = fmaf(d2, d2, acc);
        acc = fmaf(d3, d3, acc);
        #pragma unroll
        for (int o = 16; o; o >>= 1) acc += __shfl_xor_sync(0xffffffffu, acc, o);
        if (lane == 0) {
            float h = MARGIN - acc * (1.0f / Dn);
            if (h > 0.f) hinge_sum += h;
        }
    }

    if (lane == 0 && hinge_sum != 0.f) atomicAdd(&bs, hinge_sum);
    __syncthreads();
    if (threadIdx.x == 0 && bs != 0.f) atomicAdd(&g_acc2, (double)bs);
}

__global__ void finalize_kernel(float* out) {
    out[0] = (float)(g_acc1 * (1.0 / ((double)Bn * Dn)) +
                     g_acc2 * (1.0 / ((double)Bn * Cn)));
}

extern "C" void kernel_launch(void* const* d_in, const int* in_sizes, int n_in,
                              void* d_out, int out_size) {
    const float* pos = (const float*)d_in[0];  // (B, D)
    const float* neg = (const float*)d_in[1];  // (B, C, D)
    const float* lan = (const float*)d_in[2];  // (B, D)
    float* out = (float*)d_out;

    init_kernel<<<1, 1>>>();
    loss1_kernel<<<1, 256>>>(pos, lan);
    loss2_kernel<<<Bn * (Cn / 64), 256>>>(pos, neg);
    finalize_kernel<<<1, 1>>>(out);
}

// round 4
// speedup vs baseline: 1.2022x; 1.2022x over previous
#include <cuda_runtime.h>

#define Bn 256
#define Cn 4096
#define Dn 100
#define MARGIN 0.1f

#define CPB 64                    // c-rows per block
#define NB2 (Bn * (Cn / CPB))     // 16384 loss2 blocks
#define NBLK (NB2 + 1)            // + 1 loss1 block

// Scratch accumulators (zero-initialized at module load; every kernel call
// leaves them reset to zero -> deterministic across graph replays).
__device__ double g_acc1;
__device__ double g_acc2;
__device__ unsigned int g_ticket;

__global__ __launch_bounds__(256) void fused_loss_kernel(
    const float* __restrict__ pos, const float* __restrict__ neg,
    const float* __restrict__ lan, float* __restrict__ out) {

    const int tid = threadIdx.x;
    const int lane = tid & 31;
    const int warp = tid >> 5;

    if (blockIdx.x < NB2) {
        // ---------------- loss2 ----------------
        const int b = blockIdx.x >> 6;              // 64 blocks per b
        const int cbase = (blockIdx.x & 63) << 6;   // * CPB

        // pos[b,:] as 25 float4s (row stride 400 B -> 16B aligned)
        const float4* prow4 = (const float4*)(pos + b * Dn);
        float4 p = make_float4(0.f, 0.f, 0.f, 0.f);
        if (lane < 25) p = prow4[lane];

        __shared__ float bs;
        if (tid == 0) bs = 0.f;
        __syncthreads();

        float hinge_sum = 0.f;

        #pragma unroll
        for (int j = 0; j < 8; j++) {
            const int c = cbase + j * 8 + warp;
            const float4* nrow4 =
                (const float4*)(neg + ((long long)b * Cn + c) * Dn);
            float acc = 0.f;
            if (lane < 25) {
                float4 n = nrow4[lane];
                float dx = p.x - n.x, dy = p.y - n.y;
                float dz = p.z - n.z, dw = p.w - n.w;
                acc = dx * dx;
                acc = fmaf(dy, dy, acc);
                acc = fmaf(dz, dz, acc);
                acc = fmaf(dw, dw, acc);
            }
            #pragma unroll
            for (int o = 16; o; o >>= 1)
                acc += __shfl_xor_sync(0xffffffffu, acc, o);
            if (lane == 0) {
                float h = MARGIN - acc * (1.0f / Dn);
                if (h > 0.f) hinge_sum += h;
            }
        }

        if (lane == 0 && hinge_sum != 0.f) atomicAdd(&bs, hinge_sum);
        __syncthreads();
        if (tid == 0 && bs != 0.f) atomicAdd(&g_acc2, (double)bs);
    } else {
        // ---------------- loss1 (one block) ----------------
        const float4* p4 = (const float4*)pos;
        const float4* l4 = (const float4*)lan;
        float acc = 0.f;
        for (int i = tid; i < (Bn * Dn) / 4; i += blockDim.x) {
            float4 a = p4[i], b4 = l4[i];
            float dx = a.x - b4.x, dy = a.y - b4.y;
            float dz = a.z - b4.z, dw = a.w - b4.w;
            acc = fmaf(dx, dx, acc);
            acc = fmaf(dy, dy, acc);
            acc = fmaf(dz, dz, acc);
            acc = fmaf(dw, dw, acc);
        }
        #pragma unroll
        for (int o = 16; o; o >>= 1)
            acc += __shfl_xor_sync(0xffffffffu, acc, o);
        __shared__ float ws[8];
        if (lane == 0) ws[warp] = acc;
        __syncthreads();
        if (tid == 0) {
            float v = 0.f;
            #pragma unroll
            for (int w = 0; w < 8; w++) v += ws[w];
            atomicAdd(&g_acc1, (double)v);
        }
    }

    // ---------------- ticket: last block finalizes + resets ----------------
    __syncthreads();
    if (tid == 0) {
        __threadfence();
        unsigned int t = atomicAdd(&g_ticket, 1u);
        if (t == NBLK - 1) {
            __threadfence();
            double a1 = *((volatile double*)&g_acc1);
            double a2 = *((volatile double*)&g_acc2);
            out[0] = (float)(a1 * (1.0 / ((double)Bn * Dn)) +
                             a2 * (1.0 / ((double)Bn * Cn)));
            // reset for next (deterministic) call / graph replay
            g_acc1 = 0.0;
            g_acc2 = 0.0;
            __threadfence();
            g_ticket = 0u;
        }
    }
}

extern "C" void kernel_launch(void* const* d_in, const int* in_sizes, int n_in,
                              void* d_out, int out_size) {
    const float* pos = (const float*)d_in[0];  // (B, D)
    const float* neg = (const float*)d_in[1];  // (B, C, D)
    const float* lan = (const float*)d_in[2];  // (B, D)
    float* out = (float*)d_out;

    fused_loss_kernel<<<NBLK, 256>>>(pos, neg, lan, out);
}